// round 13
// baseline (speedup 1.0000x reference)
#include <cuda_runtime.h>
#include <cuda_bf16.h>
#include <cstdint>

// RBFN: out[n] = b + sum_c W_c * exp(-sigma_c^2 * max(||x_n||^2 + ||c_c||^2 - 2 x_n.c_c, 0))
// N=131072, D=64, C=512.  ldmatrix + mma.sync.m16n8k16 bf16/f32 (plain sm_103 ISA).
//
// R12 -> R13: split each nf's K-chain into two independent accumulators
// (k0,k1 -> acc ; k2,k3 -> acc2), issue order k0,k2,k1,k3 => 8 independent
// HMMA chains per warp, dep distance 8 issues. Staging back to one compact
// block at loop end (frees the 16 long-lived prefetch regs; early-LDG was
// measured neutral in R12).

#define NROWS   131072
#define DDIM    64
#define CDIM    512
#define M_TILE  128
#define NTILES  (NROWS / M_TILE)   // 1024
#define GRID    148
#define NTHREADS 512
#define NWARPS  16

#define ROW_BYTES 128   // 64 bf16 per row
#define SCREEN_T (-60.0f)

// smem layout (dynamic base is 1024-aligned)
#define SMEM_B     0                        // 512 * 128B = 65536
#define SMEM_A     (SMEM_B + 65536)         // 2 buffers * 16384
#define SMEM_KK    (SMEM_A + 2*16384)       // float2[512] = 4096
#define SMEM_WS    (SMEM_KK + 4096)         // float[512]  = 2048
#define SMEM_X2    (SMEM_WS + 2048)         // 2 * float[128] = 1024
#define SMEM_PART  (SMEM_X2 + 1024)         // 2 * float[128] = 1024
#define SMEM_TOTAL (SMEM_PART + 1024 + 128)

static __device__ __forceinline__ uint32_t smem_u32(const void* p) {
    uint32_t a;
    asm("{ .reg .u64 t; cvta.to.shared.u64 t, %1; cvt.u32.u64 %0, t; }" : "=r"(a) : "l"(p));
    return a;
}
static __device__ __forceinline__ uint32_t swz(uint32_t off) {
    return off ^ ((off >> 3) & 0x70);
}
static __device__ __forceinline__ uint32_t pack2(float a, float b) {
    __nv_bfloat162 h = __floats2bfloat162_rn(a, b);
    return *reinterpret_cast<uint32_t*>(&h);
}
static __device__ __forceinline__ float ex2f(float e) {
    float r; asm("ex2.approx.ftz.f32 %0, %1;" : "=f"(r) : "f"(e)); return r;
}
static __device__ __forceinline__ uint32_t lds32(uint32_t addr) {
    uint32_t v; asm volatile("ld.shared.b32 %0, [%1];" : "=r"(v) : "r"(addr)); return v;
}

#define STS128(addr, v) \
    asm volatile("st.shared.v4.b32 [%0], {%1,%2,%3,%4};" :: "r"(addr), "r"((v).x), "r"((v).y), "r"((v).z), "r"((v).w) : "memory")

#define LDMATRIX_X4(r0, r1, r2, r3, addr) \
    asm volatile("ldmatrix.sync.aligned.m8n8.x4.shared.b16 {%0,%1,%2,%3}, [%4];" \
        : "=r"(r0), "=r"(r1), "=r"(r2), "=r"(r3) : "r"(addr))

#define MMA16816(c0, c1, c2, c3, a0, a1, a2, a3, b0, b1) \
    asm volatile("mma.sync.aligned.m16n8k16.row.col.f32.bf16.bf16.f32 " \
        "{%0,%1,%2,%3}, {%4,%5,%6,%7}, {%8,%9}, {%0,%1,%2,%3};" \
        : "+f"(c0), "+f"(c1), "+f"(c2), "+f"(c3) \
        : "r"(a0), "r"(a1), "r"(a2), "r"(a3), "r"(b0), "r"(b1))

__global__ void __launch_bounds__(NTHREADS, 1)
rbfn_kernel(const float* __restrict__ x,
            const float* __restrict__ centres,
            const float* __restrict__ sigmas,
            const float* __restrict__ W,
            const float* __restrict__ bptr,
            float* __restrict__ out)
{
    extern __shared__ char smem[];
    const uint32_t sbase = smem_u32(smem);
    const int tid = threadIdx.x;
    const int wid = tid >> 5;
    const int lid = tid & 31;
    const int qrow = tid >> 2;      // 0..127: row for staging
    const int qq   = tid & 3;       // quarter within row

    const float LOG2E = 1.4426950408889634f;
    float2* kk12 = reinterpret_cast<float2*>(smem + SMEM_KK);
    float*  wcs  = reinterpret_cast<float*>(smem + SMEM_WS);
    float*  x2s  = reinterpret_cast<float*>(smem + SMEM_X2);   // [2][128]
    float*  part = reinterpret_cast<float*>(smem + SMEM_PART); // [2][128]

    // ---- one-time: centres -> bf16 SW128 smem, per-centre constants ----
    for (int c = tid; c < CDIM; c += NTHREADS) {
        const float4* cr = reinterpret_cast<const float4*>(centres + c * DDIM);
        float c2 = 0.f;
#pragma unroll
        for (int j = 0; j < 8; j++) {
            float4 v0 = cr[2 * j];
            float4 v1 = cr[2 * j + 1];
            c2 += v0.x * v0.x + v0.y * v0.y + v0.z * v0.z + v0.w * v0.w
                + v1.x * v1.x + v1.y * v1.y + v1.z * v1.z + v1.w * v1.w;
            uint4 pk;
            pk.x = pack2(v0.x, v0.y); pk.y = pack2(v0.z, v0.w);
            pk.z = pack2(v1.x, v1.y); pk.w = pack2(v1.z, v1.w);
            STS128(sbase + SMEM_B + swz((uint32_t)(c * ROW_BYTES + j * 16)), pk);
        }
        float s = sigmas[c];
        float s2 = s * s;
        kk12[c] = make_float2(2.f * s2 * LOG2E, -s2 * c2 * LOG2E);
        wcs[c] = W[c];
    }
    if (tid < 2 * M_TILE) part[tid] = 0.f;
    __syncthreads();

    // ---- one-time: B fragments -> registers (warp owns cols wid*32..+31) ----
    uint32_t breg[4][4][2];
#pragma unroll
    for (int nf = 0; nf < 4; nf++) {
#pragma unroll
        for (int k = 0; k < 4; k++) {
            int c = wid * 32 + nf * 8 + (lid >> 2);
            uint32_t byte0 = (uint32_t)(c * ROW_BYTES) + (uint32_t)((k * 16 + (lid & 3) * 2) * 2);
            breg[nf][k][0] = lds32(sbase + SMEM_B + swz(byte0));
            breg[nf][k][1] = lds32(sbase + SMEM_B + swz(byte0 + 16));
        }
    }

    // ---- one-time: per-lane screen thresholds t_c = (T - kk)/k1 ----
    float tv[4][2];
#pragma unroll
    for (int nf = 0; nf < 4; nf++) {
#pragma unroll
        for (int j = 0; j < 2; j++) {
            int c = wid * 32 + nf * 8 + (lid & 3) * 2 + j;
            float2 kv = kk12[c];
            tv[nf][j] = (SCREEN_T - kv.y) / kv.x;
        }
    }
    const float bval = *bptr;

    // ---- prologue: all 512 threads stage first tile into buffer 0 ----
    int tile = blockIdx.x;
    {
        const float4* xr = reinterpret_cast<const float4*>(
            x + (size_t)(tile * M_TILE + qrow) * DDIM + qq * 16);
        float4 v0 = xr[0], v1 = xr[1], v2 = xr[2], v3 = xr[3];
        float x2 = v0.x*v0.x + v0.y*v0.y + v0.z*v0.z + v0.w*v0.w
                 + v1.x*v1.x + v1.y*v1.y + v1.z*v1.z + v1.w*v1.w
                 + v2.x*v2.x + v2.y*v2.y + v2.z*v2.z + v2.w*v2.w
                 + v3.x*v3.x + v3.y*v3.y + v3.z*v3.z + v3.w*v3.w;
        uint4 pk0, pk1;
        pk0.x = pack2(v0.x, v0.y); pk0.y = pack2(v0.z, v0.w);
        pk0.z = pack2(v1.x, v1.y); pk0.w = pack2(v1.z, v1.w);
        pk1.x = pack2(v2.x, v2.y); pk1.y = pack2(v2.z, v2.w);
        pk1.z = pack2(v3.x, v3.y); pk1.w = pack2(v3.z, v3.w);
        uint32_t rb = (uint32_t)(qrow * ROW_BYTES + qq * 32);
        STS128(sbase + SMEM_A + swz(rb), pk0);
        STS128(sbase + SMEM_A + swz(rb + 16), pk1);
        x2 += __shfl_xor_sync(0xffffffffu, x2, 1);
        x2 += __shfl_xor_sync(0xffffffffu, x2, 2);
        if (qq == 0) x2s[qrow] = x2;
    }
    __syncthreads();

    int p = 0;
    int pending = -1;   // tile whose output sits in part[p^1]
    for (; tile < NTILES; tile += GRID) {
        const int next = tile + GRID;
        const uint32_t abase = sbase + SMEM_A + (uint32_t)(p * 16384);
        const float* x2cur = x2s + p * M_TILE;

        // ---- store pending tile's output from part[p^1]; re-zero it ----
        if (pending >= 0 && tid < M_TILE) {
            out[pending * M_TILE + tid] = bval + part[(p ^ 1) * M_TILE + tid];
            part[(p ^ 1) * M_TILE + tid] = 0.f;
        }

        // ---- compute current tile: 8 m-fragments; accumulate screen max ----
        float tmax = -1.f;
#pragma unroll 1
        for (int mf = 0; mf < 8; mf++) {
            uint32_t a[4][4];
            const uint32_t arow = (uint32_t)(mf * 16 + (lid & 15));
#pragma unroll
            for (int k = 0; k < 4; k++) {
                uint32_t kbyte = (uint32_t)(k * 32 + ((lid >> 4) * 16));
                LDMATRIX_X4(a[k][0], a[k][1], a[k][2], a[k][3],
                            abase + swz(arow * ROW_BYTES + kbyte));
            }

            float acc[4][4], acc2[4][4];
#pragma unroll
            for (int nf = 0; nf < 4; nf++) {
                acc[nf][0] = 0.f;  acc[nf][1] = 0.f;  acc[nf][2] = 0.f;  acc[nf][3] = 0.f;
                acc2[nf][0] = 0.f; acc2[nf][1] = 0.f; acc2[nf][2] = 0.f; acc2[nf][3] = 0.f;
            }
            // 8 independent chains: k0->acc, k2->acc2, then k1->acc, k3->acc2
#pragma unroll
            for (int nf = 0; nf < 4; nf++)
                MMA16816(acc[nf][0], acc[nf][1], acc[nf][2], acc[nf][3],
                         a[0][0], a[0][1], a[0][2], a[0][3],
                         breg[nf][0][0], breg[nf][0][1]);
#pragma unroll
            for (int nf = 0; nf < 4; nf++)
                MMA16816(acc2[nf][0], acc2[nf][1], acc2[nf][2], acc2[nf][3],
                         a[2][0], a[2][1], a[2][2], a[2][3],
                         breg[nf][2][0], breg[nf][2][1]);
#pragma unroll
            for (int nf = 0; nf < 4; nf++)
                MMA16816(acc[nf][0], acc[nf][1], acc[nf][2], acc[nf][3],
                         a[1][0], a[1][1], a[1][2], a[1][3],
                         breg[nf][1][0], breg[nf][1][1]);
#pragma unroll
            for (int nf = 0; nf < 4; nf++)
                MMA16816(acc2[nf][0], acc2[nf][1], acc2[nf][2], acc2[nf][3],
                         a[3][0], a[3][1], a[3][2], a[3][3],
                         breg[nf][3][0], breg[nf][3][1]);

            // merge halves + cheap screen; no branch here
            const int r0 = mf * 16 + (lid >> 2);
            const float hx20 = 0.5f * x2cur[r0];
            const float hx21 = 0.5f * x2cur[r0 + 8];
            float m0 = -1e30f, m1 = -1e30f;
#pragma unroll
            for (int nf = 0; nf < 4; nf++) {
                float s00 = acc[nf][0] + acc2[nf][0];
                float s01 = acc[nf][1] + acc2[nf][1];
                float s10 = acc[nf][2] + acc2[nf][2];
                float s11 = acc[nf][3] + acc2[nf][3];
                m0 = fmaxf(m0, fmaxf(s00 - tv[nf][0], s01 - tv[nf][1]));
                m1 = fmaxf(m1, fmaxf(s10 - tv[nf][0], s11 - tv[nf][1]));
            }
            tmax = fmaxf(tmax, fmaxf(m0 - hx20, m1 - hx21));
        }

        // ---- single rare-path branch per tile (P ~ 4e-10): recompute ----
        if (__any_sync(0xffffffffu, tmax > 0.f)) {
#pragma unroll 1
            for (int mf = 0; mf < 8; mf++) {
                uint32_t a[4][4];
                const uint32_t arow = (uint32_t)(mf * 16 + (lid & 15));
#pragma unroll
                for (int k = 0; k < 4; k++) {
                    uint32_t kbyte = (uint32_t)(k * 32 + ((lid >> 4) * 16));
                    LDMATRIX_X4(a[k][0], a[k][1], a[k][2], a[k][3],
                                abase + swz(arow * ROW_BYTES + kbyte));
                }
                float acc[4][4];
#pragma unroll
                for (int nf = 0; nf < 4; nf++) {
                    acc[nf][0] = 0.f; acc[nf][1] = 0.f; acc[nf][2] = 0.f; acc[nf][3] = 0.f;
                }
#pragma unroll
                for (int k = 0; k < 4; k++) {
#pragma unroll
                    for (int nf = 0; nf < 4; nf++) {
                        MMA16816(acc[nf][0], acc[nf][1], acc[nf][2], acc[nf][3],
                                 a[k][0], a[k][1], a[k][2], a[k][3],
                                 breg[nf][k][0], breg[nf][k][1]);
                    }
                }
                const int r0 = mf * 16 + (lid >> 2);
                const int r1 = r0 + 8;
                const float hx20 = 0.5f * x2cur[r0];
                const float hx21 = 0.5f * x2cur[r1];
#pragma unroll
                for (int nf = 0; nf < 4; nf++) {
#pragma unroll
                    for (int j = 0; j < 2; j++) {
                        int c = wid * 32 + nf * 8 + (lid & 3) * 2 + j;
                        float2 kv = kk12[c];
                        float wc = wcs[c];
                        float e0 = fmaf(kv.x, acc[nf][j]     - hx20, kv.y);
                        float e1 = fmaf(kv.x, acc[nf][2 + j] - hx21, kv.y);
                        if (e0 > SCREEN_T) atomicAdd(part + p * M_TILE + r0, ex2f(fminf(e0, 0.f)) * wc);
                        if (e1 > SCREEN_T) atomicAdd(part + p * M_TILE + r1, ex2f(fminf(e1, 0.f)) * wc);
                    }
                }
            }
        }

        // ---- stage next tile into buffer p^1 ----
        if (next < NTILES) {
            const float4* xr = reinterpret_cast<const float4*>(
                x + (size_t)(next * M_TILE + qrow) * DDIM + qq * 16);
            float4 v0 = xr[0], v1 = xr[1], v2 = xr[2], v3 = xr[3];
            float x2 = v0.x*v0.x + v0.y*v0.y + v0.z*v0.z + v0.w*v0.w
                     + v1.x*v1.x + v1.y*v1.y + v1.z*v1.z + v1.w*v1.w
                     + v2.x*v2.x + v2.y*v2.y + v2.z*v2.z + v2.w*v2.w
                     + v3.x*v3.x + v3.y*v3.y + v3.z*v3.z + v3.w*v3.w;
            uint4 pk0, pk1;
            pk0.x = pack2(v0.x, v0.y); pk0.y = pack2(v0.z, v0.w);
            pk0.z = pack2(v1.x, v1.y); pk0.w = pack2(v1.z, v1.w);
            pk1.x = pack2(v2.x, v2.y); pk1.y = pack2(v2.z, v2.w);
            pk1.z = pack2(v3.x, v3.y); pk1.w = pack2(v3.z, v3.w);
            uint32_t rb = (uint32_t)(qrow * ROW_BYTES + qq * 32);
            uint32_t nbase = sbase + SMEM_A + (uint32_t)((p ^ 1) * 16384);
            STS128(nbase + swz(rb), pk0);
            STS128(nbase + swz(rb + 16), pk1);
            x2 += __shfl_xor_sync(0xffffffffu, x2, 1);
            x2 += __shfl_xor_sync(0xffffffffu, x2, 2);
            if (qq == 0) x2s[(p ^ 1) * M_TILE + qrow] = x2;
        }

        __syncthreads();   // atomics done, next buffer staged, pending stored
        pending = tile;
        p ^= 1;
    }

    // ---- flush last tile's output ----
    if (pending >= 0 && tid < M_TILE) {
        out[pending * M_TILE + tid] = bval + part[(p ^ 1) * M_TILE + tid];
    }
}

extern "C" void kernel_launch(void* const* d_in, const int* in_sizes, int n_in,
                              void* d_out, int out_size) {
    const float* x       = (const float*)d_in[0];
    const float* centres = (const float*)d_in[1];
    const float* sigmas  = (const float*)d_in[2];
    const float* W       = (const float*)d_in[3];
    const float* b       = (const float*)d_in[4];
    float* out = (float*)d_out;

    cudaFuncSetAttribute(rbfn_kernel, cudaFuncAttributeMaxDynamicSharedMemorySize, SMEM_TOTAL);
    rbfn_kernel<<<GRID, NTHREADS, SMEM_TOTAL>>>(x, centres, sigmas, W, b, out);
}

// round 14
// speedup vs baseline: 1.0423x; 1.0423x over previous
#include <cuda_runtime.h>
#include <cuda_bf16.h>
#include <cstdint>

// RBFN: out[n] = b + sum_c W_c * exp(-sigma_c^2 * max(||x_n||^2 + ||c_c||^2 - 2 x_n.c_c, 0))
// N=131072, D=64, C=512.  ldmatrix + mma.sync.m16n8k16 bf16/f32 (plain sm_103 ISA).
//
// R13 -> R14: two independent 256-thread CTAs per SM (grid 296), each owning a
// fixed 256-column half with its own B smem, barriers and tile stream ->
// desynchronized phases, half barrier scope. Per-warp inner work identical to
// R11 (best). mf order rotated per warp. Outputs combined via global atomicAdd
// onto a memset-zeroed out buffer (skipped when partial sum is exactly 0).

#define NROWS   131072
#define DDIM    64
#define CDIM    512
#define CPER    256            // columns per CTA
#define M_TILE  128
#define NTILES  (NROWS / M_TILE)   // 1024
#define NPAIRS  148
#define GRID    (2 * NPAIRS)   // 296
#define NTHREADS 256
#define NWARPS  8

#define ROW_BYTES 128   // 64 bf16 per row
#define SCREEN_T (-60.0f)

// smem layout (dynamic base is 1024-aligned)
#define SMEM_B     0                        // 256 * 128B = 32768
#define SMEM_A     (SMEM_B + 32768)         // 2 buffers * 16384
#define SMEM_KK    (SMEM_A + 2*16384)       // float2[256] = 2048
#define SMEM_WS    (SMEM_KK + 2048)         // float[256]  = 1024
#define SMEM_X2    (SMEM_WS + 1024)         // 2 * float[128] = 1024
#define SMEM_PART  (SMEM_X2 + 1024)         // 2 * float[128] = 1024
#define SMEM_TOTAL (SMEM_PART + 1024 + 128)

static __device__ __forceinline__ uint32_t smem_u32(const void* p) {
    uint32_t a;
    asm("{ .reg .u64 t; cvta.to.shared.u64 t, %1; cvt.u32.u64 %0, t; }" : "=r"(a) : "l"(p));
    return a;
}
static __device__ __forceinline__ uint32_t swz(uint32_t off) {
    return off ^ ((off >> 3) & 0x70);
}
static __device__ __forceinline__ uint32_t pack2(float a, float b) {
    __nv_bfloat162 h = __floats2bfloat162_rn(a, b);
    return *reinterpret_cast<uint32_t*>(&h);
}
static __device__ __forceinline__ float ex2f(float e) {
    float r; asm("ex2.approx.ftz.f32 %0, %1;" : "=f"(r) : "f"(e)); return r;
}
static __device__ __forceinline__ uint32_t lds32(uint32_t addr) {
    uint32_t v; asm volatile("ld.shared.b32 %0, [%1];" : "=r"(v) : "r"(addr)); return v;
}

#define STS128(addr, v) \
    asm volatile("st.shared.v4.b32 [%0], {%1,%2,%3,%4};" :: "r"(addr), "r"((v).x), "r"((v).y), "r"((v).z), "r"((v).w) : "memory")

#define LDMATRIX_X4(r0, r1, r2, r3, addr) \
    asm volatile("ldmatrix.sync.aligned.m8n8.x4.shared.b16 {%0,%1,%2,%3}, [%4];" \
        : "=r"(r0), "=r"(r1), "=r"(r2), "=r"(r3) : "r"(addr))

#define MMA16816(c0, c1, c2, c3, a0, a1, a2, a3, b0, b1) \
    asm volatile("mma.sync.aligned.m16n8k16.row.col.f32.bf16.bf16.f32 " \
        "{%0,%1,%2,%3}, {%4,%5,%6,%7}, {%8,%9}, {%0,%1,%2,%3};" \
        : "+f"(c0), "+f"(c1), "+f"(c2), "+f"(c3) \
        : "r"(a0), "r"(a1), "r"(a2), "r"(a3), "r"(b0), "r"(b1))

__global__ void __launch_bounds__(NTHREADS, 2)
rbfn_kernel(const float* __restrict__ x,
            const float* __restrict__ centres,
            const float* __restrict__ sigmas,
            const float* __restrict__ W,
            const float* __restrict__ bptr,
            float* __restrict__ out)
{
    extern __shared__ char smem[];
    const uint32_t sbase = smem_u32(smem);
    const int tid = threadIdx.x;
    const int wid = tid >> 5;          // 0..7
    const int lid = tid & 31;
    const int hrow = tid >> 1;         // 0..127: row for staging
    const int hh   = tid & 1;          // half-row (32 floats) within row
    const int chalf = blockIdx.x & 1;  // which 256-column half this CTA owns
    const int pair  = blockIdx.x >> 1; // 0..147: tile stream id

    const float LOG2E = 1.4426950408889634f;
    float2* kk12 = reinterpret_cast<float2*>(smem + SMEM_KK);  // [256] local
    float*  wcs  = reinterpret_cast<float*>(smem + SMEM_WS);   // [256] local
    float*  x2s  = reinterpret_cast<float*>(smem + SMEM_X2);   // [2][128]
    float*  part = reinterpret_cast<float*>(smem + SMEM_PART); // [2][128]

    // ---- one-time: this CTA's 256 centres -> bf16 SW128 smem + constants ----
    {
        const int c_local = tid;                    // one centre per thread
        const int c = chalf * CPER + c_local;
        const float4* cr = reinterpret_cast<const float4*>(centres + c * DDIM);
        float c2 = 0.f;
#pragma unroll
        for (int j = 0; j < 8; j++) {
            float4 v0 = cr[2 * j];
            float4 v1 = cr[2 * j + 1];
            c2 += v0.x * v0.x + v0.y * v0.y + v0.z * v0.z + v0.w * v0.w
                + v1.x * v1.x + v1.y * v1.y + v1.z * v1.z + v1.w * v1.w;
            uint4 pk;
            pk.x = pack2(v0.x, v0.y); pk.y = pack2(v0.z, v0.w);
            pk.z = pack2(v1.x, v1.y); pk.w = pack2(v1.z, v1.w);
            STS128(sbase + SMEM_B + swz((uint32_t)(c_local * ROW_BYTES + j * 16)), pk);
        }
        float s = sigmas[c];
        float s2 = s * s;
        kk12[c_local] = make_float2(2.f * s2 * LOG2E, -s2 * c2 * LOG2E);
        wcs[c_local] = W[c];
    }
    if (tid < 2 * M_TILE) part[tid] = 0.f;
    __syncthreads();

    // ---- one-time: B fragments -> registers (warp owns local cols wid*32..+31) ----
    uint32_t breg[4][4][2];
#pragma unroll
    for (int nf = 0; nf < 4; nf++) {
#pragma unroll
        for (int k = 0; k < 4; k++) {
            int cl = wid * 32 + nf * 8 + (lid >> 2);
            uint32_t byte0 = (uint32_t)(cl * ROW_BYTES) + (uint32_t)((k * 16 + (lid & 3) * 2) * 2);
            breg[nf][k][0] = lds32(sbase + SMEM_B + swz(byte0));
            breg[nf][k][1] = lds32(sbase + SMEM_B + swz(byte0 + 16));
        }
    }

    // ---- one-time: per-lane screen thresholds t_c = (T - kk)/k1 ----
    float tv[4][2];
#pragma unroll
    for (int nf = 0; nf < 4; nf++) {
#pragma unroll
        for (int j = 0; j < 2; j++) {
            int cl = wid * 32 + nf * 8 + (lid & 3) * 2 + j;
            float2 kv = kk12[cl];
            tv[nf][j] = (SCREEN_T - kv.y) / kv.x;
        }
    }
    const float bhalf = (chalf == 0) ? (*bptr) : 0.f;

    // ---- prologue: 256 threads stage first tile into buffer 0 (half-row each) ----
    int tile = pair;
    {
        const float4* xr = reinterpret_cast<const float4*>(
            x + (size_t)(tile * M_TILE + hrow) * DDIM + hh * 32);
        float4 v0 = xr[0], v1 = xr[1], v2 = xr[2], v3 = xr[3];
        float x2 = v0.x*v0.x + v0.y*v0.y + v0.z*v0.z + v0.w*v0.w
                 + v1.x*v1.x + v1.y*v1.y + v1.z*v1.z + v1.w*v1.w
                 + v2.x*v2.x + v2.y*v2.y + v2.z*v2.z + v2.w*v2.w
                 + v3.x*v3.x + v3.y*v3.y + v3.z*v3.z + v3.w*v3.w;
        uint4 pk0, pk1;
        pk0.x = pack2(v0.x, v0.y); pk0.y = pack2(v0.z, v0.w);
        pk0.z = pack2(v1.x, v1.y); pk0.w = pack2(v1.z, v1.w);
        pk1.x = pack2(v2.x, v2.y); pk1.y = pack2(v2.z, v2.w);
        pk1.z = pack2(v3.x, v3.y); pk1.w = pack2(v3.z, v3.w);
        uint32_t rb = (uint32_t)(hrow * ROW_BYTES + hh * 64);
        STS128(sbase + SMEM_A + swz(rb), pk0);
        STS128(sbase + SMEM_A + swz(rb + 16), pk1);
        x2 += __shfl_xor_sync(0xffffffffu, x2, 1);
        if (hh == 0) x2s[hrow] = x2;
    }
    __syncthreads();

    int p = 0;
    int pending = -1;   // tile whose partial sums sit in part[p^1]
    for (; tile < NTILES; tile += NPAIRS) {
        const int next = tile + NPAIRS;
        const uint32_t abase = sbase + SMEM_A + (uint32_t)(p * 16384);
        const float* x2cur = x2s + p * M_TILE;

        // ---- flush pending tile: global atomicAdd (skip exact zeros), re-zero ----
        if (pending >= 0 && tid < M_TILE) {
            float v = bhalf + part[(p ^ 1) * M_TILE + tid];
            if (v != 0.f) atomicAdd(out + pending * M_TILE + tid, v);
            part[(p ^ 1) * M_TILE + tid] = 0.f;
        }

        // ---- compute current tile: 8 m-fragments, order rotated per warp ----
#pragma unroll 1
        for (int mf = 0; mf < 8; mf++) {
            const int mfr = (mf + wid) & 7;   // desync phases across warps
            uint32_t a[4][4];
            const uint32_t arow = (uint32_t)(mfr * 16 + (lid & 15));
#pragma unroll
            for (int k = 0; k < 4; k++) {
                uint32_t kbyte = (uint32_t)(k * 32 + ((lid >> 4) * 16));
                LDMATRIX_X4(a[k][0], a[k][1], a[k][2], a[k][3],
                            abase + swz(arow * ROW_BYTES + kbyte));
            }

            float acc[4][4];
#pragma unroll
            for (int nf = 0; nf < 4; nf++) {
                acc[nf][0] = 0.f; acc[nf][1] = 0.f; acc[nf][2] = 0.f; acc[nf][3] = 0.f;
            }
#pragma unroll
            for (int k = 0; k < 4; k++) {
#pragma unroll
                for (int nf = 0; nf < 4; nf++) {
                    MMA16816(acc[nf][0], acc[nf][1], acc[nf][2], acc[nf][3],
                             a[k][0], a[k][1], a[k][2], a[k][3],
                             breg[nf][k][0], breg[nf][k][1]);
                }
            }

            // cheap screen: any e > T ?  (dot - t > 0.5*x2)
            const int r0 = mfr * 16 + (lid >> 2);
            const int r1 = r0 + 8;
            const float hx20 = 0.5f * x2cur[r0];
            const float hx21 = 0.5f * x2cur[r1];
            float m0 = fmaxf(acc[0][0] - tv[0][0], acc[0][1] - tv[0][1]);
            float m1 = fmaxf(acc[0][2] - tv[0][0], acc[0][3] - tv[0][1]);
#pragma unroll
            for (int nf = 1; nf < 4; nf++) {
                m0 = fmaxf(m0, fmaxf(acc[nf][0] - tv[nf][0], acc[nf][1] - tv[nf][1]));
                m1 = fmaxf(m1, fmaxf(acc[nf][2] - tv[nf][0], acc[nf][3] - tv[nf][1]));
            }
            bool hit = fmaxf(m0 - hx20, m1 - hx21) > 0.f;
            if (__any_sync(0xffffffffu, hit)) {   // ~never taken (P ~ 4e-10)
#pragma unroll
                for (int nf = 0; nf < 4; nf++) {
#pragma unroll
                    for (int j = 0; j < 2; j++) {
                        int cl = wid * 32 + nf * 8 + (lid & 3) * 2 + j;
                        float2 kv = kk12[cl];
                        float wc = wcs[cl];
                        float e0 = fmaf(kv.x, acc[nf][j]     - hx20, kv.y);
                        float e1 = fmaf(kv.x, acc[nf][2 + j] - hx21, kv.y);
                        if (e0 > SCREEN_T) atomicAdd(part + p * M_TILE + r0, ex2f(fminf(e0, 0.f)) * wc);
                        if (e1 > SCREEN_T) atomicAdd(part + p * M_TILE + r1, ex2f(fminf(e1, 0.f)) * wc);
                    }
                }
            }
        }

        // ---- stage next tile into buffer p^1 ----
        if (next < NTILES) {
            const float4* xr = reinterpret_cast<const float4*>(
                x + (size_t)(next * M_TILE + hrow) * DDIM + hh * 32);
            float4 v0 = xr[0], v1 = xr[1], v2 = xr[2], v3 = xr[3];
            float x2 = v0.x*v0.x + v0.y*v0.y + v0.z*v0.z + v0.w*v0.w
                     + v1.x*v1.x + v1.y*v1.y + v1.z*v1.z + v1.w*v1.w
                     + v2.x*v2.x + v2.y*v2.y + v2.z*v2.z + v2.w*v2.w
                     + v3.x*v3.x + v3.y*v3.y + v3.z*v3.z + v3.w*v3.w;
            uint4 pk0, pk1;
            pk0.x = pack2(v0.x, v0.y); pk0.y = pack2(v0.z, v0.w);
            pk0.z = pack2(v1.x, v1.y); pk0.w = pack2(v1.z, v1.w);
            pk1.x = pack2(v2.x, v2.y); pk1.y = pack2(v2.z, v2.w);
            pk1.z = pack2(v3.x, v3.y); pk1.w = pack2(v3.z, v3.w);
            uint32_t rb = (uint32_t)(hrow * ROW_BYTES + hh * 64);
            uint32_t nbase = sbase + SMEM_A + (uint32_t)((p ^ 1) * 16384);
            STS128(nbase + swz(rb), pk0);
            STS128(nbase + swz(rb + 16), pk1);
            x2 += __shfl_xor_sync(0xffffffffu, x2, 1);
            if (hh == 0) x2s[(p ^ 1) * M_TILE + hrow] = x2;
        }

        __syncthreads();   // atomics done, next buffer staged, pending flushed
        pending = tile;
        p ^= 1;
    }

    // ---- flush last tile ----
    if (pending >= 0 && tid < M_TILE) {
        float v = bhalf + part[(p ^ 1) * M_TILE + tid];
        if (v != 0.f) atomicAdd(out + pending * M_TILE + tid, v);
    }
}

extern "C" void kernel_launch(void* const* d_in, const int* in_sizes, int n_in,
                              void* d_out, int out_size) {
    const float* x       = (const float*)d_in[0];
    const float* centres = (const float*)d_in[1];
    const float* sigmas  = (const float*)d_in[2];
    const float* W       = (const float*)d_in[3];
    const float* b       = (const float*)d_in[4];
    float* out = (float*)d_out;

    // zero the output; both column-half CTAs accumulate into it
    cudaMemsetAsync(out, 0, (size_t)out_size * sizeof(float));

    cudaFuncSetAttribute(rbfn_kernel, cudaFuncAttributeMaxDynamicSharedMemorySize, SMEM_TOTAL);
    rbfn_kernel<<<GRID, NTHREADS, SMEM_TOTAL>>>(x, centres, sigmas, W, b, out);
}